// round 3
// baseline (speedup 1.0000x reference)
#include <cuda_runtime.h>
#include <cstdint>

// Problem constants (match reference)
#define BB   16
#define CC   3
#define HH   512
#define WW   512
#define CUT  224
#define CUTN 32
#define ROWS_PER_CHUNK 56   // 224 / 4 chunks

__global__ __launch_bounds__(CUT) void make_cutouts_kernel(
    const float* __restrict__ x,
    const int*   __restrict__ sizes,
    const int*   __restrict__ offx,
    const int*   __restrict__ offy,
    float*       __restrict__ out)
{
    const int n     = blockIdx.x;   // cut index      [0, 32)
    const int bc    = blockIdx.y;   // b*C + c        [0, 48)
    const int chunk = blockIdx.z;   // row chunk      [0, 4)
    const int j     = threadIdx.x;  // output column  [0, 224)

    __shared__ int s_xidx[CUT];
    __shared__ int s_yidx[CUT];

    const int  sz = sizes[n];
    const int  ox = offx[n];
    const int  oy = offy[n];

    // Precompute gather indices once per block (j < CUT always, blockDim == 224)
    s_xidx[j] = ox + (j * sz) / CUT;
    s_yidx[j] = oy + (j * sz) / CUT;
    __syncthreads();

    const int xj = s_xidx[j];

    const float* __restrict__ xplane = x + (size_t)bc * (HH * WW);
    float* __restrict__ oplane =
        out + ((size_t)n * (BB * CC) + bc) * (size_t)(CUT * CUT);

    const int i0 = chunk * ROWS_PER_CHUNK;

    #pragma unroll 4
    for (int r = 0; r < ROWS_PER_CHUNK; ++r) {
        const int i  = i0 + r;
        const int yi = s_yidx[i];
        oplane[(size_t)i * CUT + j] = xplane[(size_t)yi * WW + xj];
    }
}

extern "C" void kernel_launch(void* const* d_in, const int* in_sizes, int n_in,
                              void* d_out, int out_size)
{
    const float* x     = (const float*)d_in[0];
    const int*   sizes = (const int*)d_in[1];
    const int*   ox    = (const int*)d_in[2];
    const int*   oy    = (const int*)d_in[3];
    float*       out   = (float*)d_out;

    dim3 grid(CUTN, BB * CC, CUT / ROWS_PER_CHUNK);
    dim3 block(CUT);
    make_cutouts_kernel<<<grid, block>>>(x, sizes, ox, oy, out);
}

// round 4
// speedup vs baseline: 1.0749x; 1.0749x over previous
#include <cuda_runtime.h>
#include <cstdint>

#define BB   16
#define CC   3
#define HH   512
#define WW   512
#define CUT  224
#define CUTN 32

// Block: 224 threads = 56 column-groups (4 cols each, float4 store) x 4 rows.
// Each block iterates 8 times -> covers 32 rows. gridDim.z = 224/32 = 7.
#define ROWS_PER_BLOCK 32
#define ITERS 8

__global__ __launch_bounds__(224) void make_cutouts_kernel(
    const float* __restrict__ x,
    const int*   __restrict__ sizes,
    const int*   __restrict__ offx,
    const int*   __restrict__ offy,
    float*       __restrict__ out)
{
    const int n     = blockIdx.x;   // cut index   [0, 32)
    const int bc    = blockIdx.y;   // b*C + c     [0, 48)
    const int chunk = blockIdx.z;   // row chunk   [0, 7)

    const int tid  = threadIdx.x;
    const int jg   = tid % 56;      // column group: cols 4*jg .. 4*jg+3
    const int rsub = tid / 56;      // row sub-offset 0..3

    const int sz = sizes[n];
    const int ox = offx[n];
    const int oy = offy[n];

    // Gather column indices for this thread's 4 output columns (register-resident)
    const int c0  = jg * 4;
    const int xi0 = ox + ( c0      * sz) / CUT;
    const int xi1 = ox + ((c0 + 1) * sz) / CUT;
    const int xi2 = ox + ((c0 + 2) * sz) / CUT;
    const int xi3 = ox + ((c0 + 3) * sz) / CUT;

    const float* __restrict__ xplane = x + (size_t)bc * (HH * WW);
    float4* __restrict__ oplane =
        (float4*)(out + ((size_t)n * (BB * CC) + bc) * (size_t)(CUT * CUT));

    const int i0 = chunk * ROWS_PER_BLOCK + rsub;

    #pragma unroll 4
    for (int it = 0; it < ITERS; ++it) {
        const int i  = i0 + it * 4;
        const int yi = oy + (i * sz) / CUT;
        const float* __restrict__ row = xplane + (size_t)yi * WW;

        float4 v;
        v.x = __ldg(row + xi0);
        v.y = __ldg(row + xi1);
        v.z = __ldg(row + xi2);
        v.w = __ldg(row + xi3);

        // Streaming store: output is write-once/dead -> evict-first, keep x in L2
        __stcs(&oplane[(size_t)i * 56 + jg], v);
    }
}

extern "C" void kernel_launch(void* const* d_in, const int* in_sizes, int n_in,
                              void* d_out, int out_size)
{
    const float* x     = (const float*)d_in[0];
    const int*   sizes = (const int*)d_in[1];
    const int*   ox    = (const int*)d_in[2];
    const int*   oy    = (const int*)d_in[3];
    float*       out   = (float*)d_out;

    dim3 grid(CUTN, BB * CC, CUT / ROWS_PER_BLOCK);
    dim3 block(224);
    make_cutouts_kernel<<<grid, block>>>(x, sizes, ox, oy, out);
}